// round 3
// baseline (speedup 1.0000x reference)
#include <cuda_runtime.h>
#include <cuda_bf16.h>

// Problem constants
#define Uu 8192
#define Ii 4096
#define Kk 256
#define NNZ 409600

static __device__ __align__(16) float g_E1[Uu * Kk];     // adj @ (item_sv_f/lam_pos)
static __device__ __align__(16) float g_E2[Uu * Kk];     // norm_adj @ G_i
static __device__ __align__(16) float g_Gu[Uu * Kk];     // user_sv_gnn
static __device__ __align__(16) float g_Gi[Ii * Kk];     // item_sv_gnn / lambda
static __device__ __align__(16) float g_Cf[Ii * Kk];     // item_sv_f / lam_pos
static __device__ __align__(16) float g_Df[Kk * Ii];     // user_sv_f[:I]^T
static __device__ __align__(16) float g_S[Kk * Ii];      // G_u^T @ pos_dense
static __device__ unsigned g_colmin[Ii];
static __device__ float    g_colsum[Ii];
static __device__ int      g_minkey[Uu];
static __device__ int      g_rowstart[Uu];
static __device__ int      g_rowcnt[Uu];
static __device__ int      g_colcnt[Ii];
static __device__ int      g_coloff[Ii];
static __device__ int      g_colcur[Ii];
static __device__ int      g_colperm[NNZ];
static __device__ float    g_p1[Uu], g_p2[Uu];
static __device__ int      g_c1[Uu], g_c2[Uu];
static __device__ int      g_has[Uu];

#define INV_COEFF (1.0f / 5792.6187514801984f)   // 1/sqrt(U*I)

__device__ __forceinline__ unsigned fenc(float f) {
    unsigned u = __float_as_uint(f);
    return (u & 0x80000000u) ? ~u : (u | 0x80000000u);
}
__device__ __forceinline__ float fdec(unsigned e) {
    return (e & 0x80000000u) ? __uint_as_float(e ^ 0x80000000u) : __uint_as_float(~e);
}

// ---------------------------------------------------------------- init
__global__ void init_kernel() {
    int i = blockIdx.x * blockDim.x + threadIdx.x;
    if (i < Ii) { g_colmin[i] = 0xFFFFFFFFu; g_colsum[i] = 0.0f; g_colcnt[i] = 0; }
    if (i < Uu) { g_minkey[i] = 0x7FFFFFFF; g_rowcnt[i] = 0; g_rowstart[i] = 0; }
}

// ------------------------------------------------- build row/col metadata
__global__ void build_kernel(const int* __restrict__ pos_rows,
                             const int* __restrict__ pos_cols) {
    int i = blockIdx.x * blockDim.x + threadIdx.x;
    if (i >= NNZ) return;
    int r = pos_rows[i], c = pos_cols[i];
    atomicAdd(&g_rowcnt[r], 1);
    atomicAdd(&g_colcnt[c], 1);
    if (i == 0 || pos_rows[i - 1] != r) g_rowstart[r] = i;
    atomicMin(&g_minkey[r], c * NNZ + i);
}

// --------------------------------- exclusive scan of column counts (1 block)
__global__ void col_scan_kernel() {
    __shared__ int partial[256];
    int t = threadIdx.x;
    int local[16];
    int s = 0;
#pragma unroll
    for (int j = 0; j < 16; j++) { local[j] = s; s += g_colcnt[t * 16 + j]; }
    partial[t] = s;
    __syncthreads();
    if (t == 0) {
        int run = 0;
        for (int i = 0; i < 256; i++) { int v = partial[i]; partial[i] = run; run += v; }
    }
    __syncthreads();
    int base = partial[t];
#pragma unroll
    for (int j = 0; j < 16; j++) {
        int off = base + local[j];
        g_coloff[t * 16 + j] = off;
        g_colcur[t * 16 + j] = off;
    }
}

// ----------------------------------------- scatter indices sorted by column
__global__ void scatter_kernel(const int* __restrict__ pos_cols) {
    int i = blockIdx.x * blockDim.x + threadIdx.x;
    if (i >= NNZ) return;
    int c = pos_cols[i];
    int p = atomicAdd(&g_colcur[c], 1);
    g_colperm[p] = i;
}

// ---------------------------------------------- Cf = item_sv_f / lam_pos
__global__ void cf_kernel(const float* __restrict__ item_sv_f,
                          const float* __restrict__ lam_pos) {
    int i = blockIdx.x * blockDim.x + threadIdx.x;
    if (i < Ii * Kk) g_Cf[i] = item_sv_f[i] / lam_pos[i & (Kk - 1)];
}

// ------------------------------------- Df = transpose(user_sv_f[:I]) [K, I]
__global__ void transpose_kernel(const float* __restrict__ usf) {
    __shared__ float t[32][33];
    int bx = blockIdx.x, by = blockIdx.y;
    int tx = threadIdx.x, ty = threadIdx.y;
    int c_in = bx * 32 + ty, k_in = by * 32 + tx;
    t[ty][tx] = usf[c_in * Kk + k_in];
    __syncthreads();
    int c_out = bx * 32 + tx, k_out = by * 32 + ty;
    g_Df[k_out * Ii + c_out] = t[tx][ty];
}

// ------------------------------------- user GNN: G_u (rows are presorted)
__global__ void user_gnn_kernel(const int* __restrict__ pos_cols,
                                const float* __restrict__ pos_vals,
                                const float* __restrict__ item_sv,
                                const float* __restrict__ user_sv) {
    int r = blockIdx.x, k = threadIdx.x;
    int s0 = g_rowstart[r], n = g_rowcnt[r];
    __shared__ int sc[256];
    __shared__ float sv[256];
    float acc = 0.0f;
    for (int base = 0; base < n; base += 256) {
        int j = base + k;
        if (j < n) { sc[k] = pos_cols[s0 + j]; sv[k] = pos_vals[s0 + j]; }
        __syncthreads();
        int lim = min(256, n - base);
        for (int jj = 0; jj < lim; jj++)
            acc += sv[jj] * item_sv[sc[jj] * Kk + k];
        __syncthreads();
    }
    g_Gu[r * Kk + k] = 0.5f * (acc * INV_COEFF + user_sv[r * Kk + k]);
}

// ------------- fused item GNN (G_i with /lambda folded) + S = G_u^T @ pos
__global__ void item_s_kernel(const int* __restrict__ pos_rows,
                              const float* __restrict__ pos_vals,
                              const float* __restrict__ user_sv,
                              const float* __restrict__ item_sv,
                              const float* __restrict__ lambda_mat) {
    int c = blockIdx.x, k = threadIdx.x;
    int s0 = g_coloff[c], n = g_colcnt[c];
    __shared__ int sr[256];
    __shared__ float sv[256];
    float accI = 0.0f, accS = 0.0f;
    for (int base = 0; base < n; base += 256) {
        int j = base + k;
        if (j < n) {
            int p = g_colperm[s0 + j];
            sr[k] = pos_rows[p];
            sv[k] = pos_vals[p];
        }
        __syncthreads();
        int lim = min(256, n - base);
        for (int jj = 0; jj < lim; jj++) {
            int r = sr[jj];
            float v = sv[jj];
            accI += v * user_sv[r * Kk + k];
            accS += v * g_Gu[r * Kk + k];
        }
        __syncthreads();
    }
    g_Gi[c * Kk + k] = 0.5f * (accI * INV_COEFF + item_sv[c * Kk + k]) / lambda_mat[k];
    g_S[k * Ii + c] = accS;   // strided write, 4 MB total — cheap
}

// ----------------------------------------------------------- tiled GEMM
// C[M,N] = A[M,KD] * B[KD,N], all row-major. MODE 0: store C.
// MODE 1: no store; per-column min & sum atomically reduced (mat_expo stats).
template <int BM, int BN, int BK, int TM, int TN, int MODE>
__global__ void gemm_nn(int M, int N, int KD,
                        const float* __restrict__ A,
                        const float* __restrict__ B,
                        float* __restrict__ C,
                        unsigned* cmin, float* csum) {
    constexpr int THREADS = (BM / TM) * (BN / TN);
    __shared__ float As[BK][BM];
    __shared__ float Bs[BK][BN];
    int tid = threadIdx.x;
    int n0 = blockIdx.x * BN, m0 = blockIdx.y * BM;
    int tx = tid % (BN / TN), ty = tid / (BN / TN);
    float acc[TM][TN];
#pragma unroll
    for (int i = 0; i < TM; i++)
#pragma unroll
        for (int j = 0; j < TN; j++) acc[i][j] = 0.0f;

    for (int k0 = 0; k0 < KD; k0 += BK) {
#pragma unroll
        for (int l = 0; l < BM * BK / (THREADS * 4); l++) {
            int f = tid + l * THREADS;
            int row = f / (BK / 4), kq = f % (BK / 4);
            float4 v = *(const float4*)&A[(m0 + row) * KD + k0 + kq * 4];
            As[kq * 4 + 0][row] = v.x;
            As[kq * 4 + 1][row] = v.y;
            As[kq * 4 + 2][row] = v.z;
            As[kq * 4 + 3][row] = v.w;
        }
#pragma unroll
        for (int l = 0; l < BK * BN / (THREADS * 4); l++) {
            int f = tid + l * THREADS;
            int kr = f / (BN / 4), nq = f % (BN / 4);
            *(float4*)&Bs[kr][nq * 4] = *(const float4*)&B[(k0 + kr) * N + n0 + nq * 4];
        }
        __syncthreads();
#pragma unroll
        for (int kk = 0; kk < BK; kk++) {
            float a[TM], b[TN];
#pragma unroll
            for (int i = 0; i < TM; i++) a[i] = As[kk][ty * TM + i];
#pragma unroll
            for (int j = 0; j < TN; j++) b[j] = Bs[kk][tx * TN + j];
#pragma unroll
            for (int i = 0; i < TM; i++)
#pragma unroll
                for (int j = 0; j < TN; j++) acc[i][j] += a[i] * b[j];
        }
        __syncthreads();
    }

    if (MODE == 0) {
#pragma unroll
        for (int i = 0; i < TM; i++) {
            int m = m0 + ty * TM + i;
#pragma unroll
            for (int j = 0; j < TN; j += 4) {
                float4 v = make_float4(acc[i][j], acc[i][j + 1], acc[i][j + 2], acc[i][j + 3]);
                *(float4*)&C[m * N + n0 + tx * TN + j] = v;
            }
        }
    } else {
#pragma unroll
        for (int j = 0; j < TN; j++) {
            float mn = acc[0][j], sm = 0.0f;
#pragma unroll
            for (int i = 0; i < TM; i++) { mn = fminf(mn, acc[i][j]); sm += acc[i][j]; }
            int col = n0 + tx * TN + j;
            atomicMin(&cmin[col], fenc(mn));
            atomicAdd(&csum[col], sm);
        }
    }
}

// ------------------- per-row mat_expo entries -> p1/p2 (compute_P fusion)
__global__ void entry_kernel(const int* __restrict__ pos_cols,
                             const float* __restrict__ pos_vals,
                             const float* __restrict__ usf) {
    int r = blockIdx.x, t = threadIdx.x;
    int mk = g_minkey[r];
    if (mk == 0x7FFFFFFF) { if (t == 0) g_has[r] = 0; return; }
    int eidx = mk % NNZ;
    int c1 = pos_cols[eidx];
    float v1 = pos_vals[eidx];
    int c2 = (c1 + 1) & (Ii - 1);
    float a = g_E1[r * Kk + t];
    float e1 = a * usf[c1 * Kk + t];
    float e2 = a * usf[c2 * Kk + t];
    __shared__ float s1[256], s2[256];
    s1[t] = e1; s2[t] = e2;
    __syncthreads();
    for (int off = 128; off > 0; off >>= 1) {
        if (t < off) { s1[t] += s1[t + off]; s2[t] += s2[t + off]; }
        __syncthreads();
    }
    if (t == 0) {
        float E1v = s1[0], E2v = s2[0];
        float m1 = fdec(g_colmin[c1]), m2 = fdec(g_colmin[c2]);
        float sum1 = g_colsum[c1] - (float)Uu * m1 + (float)Uu * 1e-8f;
        float sum2 = g_colsum[c2] - (float)Uu * m2 + (float)Uu * 1e-8f;
        float n1 = (E1v - m1 + 1e-8f) / sum1;
        float n2 = (E2v - m2 + 1e-8f) / sum2;
        float d1 = (v1 == 0.0f) ? 1e-5f : v1;
        float d2 = (v1 == 0.0f) ? 1e-5f : -v1;
        g_p1[r] = n1 / d1;
        g_p2[r] = n2 / d2;
        g_c1[r] = c1;
        g_c2[r] = c2;
        g_has[r] = 1;
    }
}

// ------------------------------------------- out += 0.2 * mat_adjust
__global__ void adjust_kernel(float* __restrict__ out) {
    int r = blockIdx.x * blockDim.x + threadIdx.x;
    if (r >= Uu || !g_has[r]) return;
    out[r * Ii + g_c1[r]] += 0.2f * g_p1[r];
    out[r * Ii + g_c2[r]] += 0.2f * g_p2[r];
}

extern "C" void kernel_launch(void* const* d_in, const int* in_sizes, int n_in,
                              void* d_out, int out_size) {
    const float* adj       = (const float*)d_in[0];
    const float* norm_adj  = (const float*)d_in[1];
    const float* user_sv   = (const float*)d_in[2];
    const float* item_sv   = (const float*)d_in[3];
    const float* user_sv_f = (const float*)d_in[4];
    const float* item_sv_f = (const float*)d_in[5];
    const int*   pos_rows  = (const int*)d_in[6];
    const int*   pos_cols  = (const int*)d_in[7];
    const float* pos_vals  = (const float*)d_in[8];
    const float* lambda_m  = (const float*)d_in[9];
    const float* lambda_p  = (const float*)d_in[10];
    float* out = (float*)d_out;

    float *E1, *E2, *Cf, *Df, *S, *Gi;
    unsigned* cmin;
    float* csum;
    cudaGetSymbolAddress((void**)&E1, g_E1);
    cudaGetSymbolAddress((void**)&E2, g_E2);
    cudaGetSymbolAddress((void**)&Cf, g_Cf);
    cudaGetSymbolAddress((void**)&Df, g_Df);
    cudaGetSymbolAddress((void**)&S, g_S);
    cudaGetSymbolAddress((void**)&Gi, g_Gi);
    cudaGetSymbolAddress((void**)&cmin, g_colmin);
    cudaGetSymbolAddress((void**)&csum, g_colsum);

    // 1. init metadata
    init_kernel<<<Uu / 256, 256>>>();
    // 2. row/col counts, row starts, per-row min key
    build_kernel<<<(NNZ + 255) / 256, 256>>>(pos_rows, pos_cols);
    // 3. column offsets (counting sort)
    col_scan_kernel<<<1, 256>>>();
    // 4. column-sorted permutation
    scatter_kernel<<<(NNZ + 255) / 256, 256>>>(pos_cols);
    // 5. Cf and Df prep
    cf_kernel<<<(Ii * Kk + 255) / 256, 256>>>(item_sv_f, lambda_p);
    transpose_kernel<<<dim3(Ii / 32, Kk / 32), dim3(32, 32)>>>(user_sv_f);
    // 6. user GNN smoothing
    user_gnn_kernel<<<Uu, 256>>>(pos_cols, pos_vals, item_sv, user_sv);
    // 7. fused item GNN + SpMM S = G_u^T @ pos_dense
    item_s_kernel<<<Ii, 256>>>(pos_rows, pos_vals, user_sv, item_sv, lambda_m);
    // 8. E1 = adj @ Cf                 [8192,4096]@[4096,256]
    gemm_nn<128, 64, 16, 8, 4, 0><<<dim3(Kk / 64, Uu / 128), 256>>>(
        Uu, Kk, Ii, adj, Cf, E1, nullptr, nullptr);
    // 9. E2 = norm_adj @ Gi            [8192,4096]@[4096,256]
    gemm_nn<128, 64, 16, 8, 4, 0><<<dim3(Kk / 64, Uu / 128), 256>>>(
        Uu, Kk, Ii, norm_adj, Gi, E2, nullptr, nullptr);
    // 10. mat_expo col stats: (E1 @ Df) fused min/sum, no store
    gemm_nn<128, 128, 16, 8, 8, 1><<<dim3(Ii / 128, Uu / 128), 256>>>(
        Uu, Ii, Kk, E1, Df, nullptr, cmin, csum);
    // 11. per-row mat_expo entries -> p1/p2
    entry_kernel<<<Uu, 256>>>(pos_cols, pos_vals, user_sv_f);
    // 12. out = E2 @ S                 [8192,256]@[256,4096]
    gemm_nn<128, 128, 16, 8, 8, 0><<<dim3(Ii / 128, Uu / 128), 256>>>(
        Uu, Ii, Kk, E2, S, out, nullptr, nullptr);
    // 13. out += 0.2 * mat_adjust
    adjust_kernel<<<Uu / 256, 256>>>(out);
}

// round 6
// speedup vs baseline: 2.0227x; 2.0227x over previous
#include <cuda_runtime.h>
#include <cuda_bf16.h>
#include <cstdint>

// Problem constants
#define Uu 8192
#define Ii 4096
#define Kk 256
#define NNZ 409600
#define INV_COEFF (1.0f / 5792.6187514801984f)   // 1/sqrt(U*I)

// ===================== device scratch ======================================
// bf16 hi/lo planes for all GEMM operands
static __device__ __align__(16) __nv_bfloat16 g_adjH[(size_t)Uu * Ii];
static __device__ __align__(16) __nv_bfloat16 g_adjL[(size_t)Uu * Ii];
static __device__ __align__(16) __nv_bfloat16 g_nrmH[(size_t)Uu * Ii];
static __device__ __align__(16) __nv_bfloat16 g_nrmL[(size_t)Uu * Ii];
static __device__ __align__(16) __nv_bfloat16 g_CfTH[Kk * Ii], g_CfTL[Kk * Ii];
static __device__ __align__(16) __nv_bfloat16 g_GiTH[Kk * Ii], g_GiTL[Kk * Ii];
static __device__ __align__(16) __nv_bfloat16 g_usfH[Ii * Kk], g_usfL[Ii * Kk];
static __device__ __align__(16) __nv_bfloat16 g_StH[Ii * Kk],  g_StL[Ii * Kk];
static __device__ __align__(16) __nv_bfloat16 g_E1H[Uu * Kk],  g_E1L[Uu * Kk];
static __device__ __align__(16) __nv_bfloat16 g_E2H[Uu * Kk],  g_E2L[Uu * Kk];
static __device__ __align__(16) float g_E1[Uu * Kk];
static __device__ __align__(16) float g_E2[Uu * Kk];
static __device__ __align__(16) float g_Gu[Uu * Kk];
static __device__ unsigned g_colmin[Ii];
static __device__ float    g_colsum[Ii];
static __device__ int      g_minkey[Uu];
static __device__ int      g_rowstart[Uu];
static __device__ int      g_rowcnt[Uu];
static __device__ int      g_colcnt[Ii];
static __device__ int      g_coloff[Ii];
static __device__ int      g_colcur[Ii];
static __device__ int      g_colperm[NNZ];
static __device__ float    g_p1[Uu], g_p2[Uu];
static __device__ int      g_c1[Uu], g_c2[Uu];
static __device__ int      g_has[Uu];

__device__ __forceinline__ unsigned fenc(float f) {
    unsigned u = __float_as_uint(f);
    return (u & 0x80000000u) ? ~u : (u | 0x80000000u);
}
__device__ __forceinline__ float fdec(unsigned e) {
    return (e & 0x80000000u) ? __uint_as_float(e ^ 0x80000000u) : __uint_as_float(~e);
}

// ---------------------------------------------------------------- init
__global__ void init_kernel() {
    int i = blockIdx.x * blockDim.x + threadIdx.x;
    if (i < Ii) { g_colmin[i] = 0xFFFFFFFFu; g_colsum[i] = 0.0f; g_colcnt[i] = 0; }
    if (i < Uu) { g_minkey[i] = 0x7FFFFFFF; g_rowcnt[i] = 0; g_rowstart[i] = 0; }
}

// ------------------------------------------------- build row/col metadata
__global__ void build_kernel(const int* __restrict__ pos_rows,
                             const int* __restrict__ pos_cols) {
    int i = blockIdx.x * blockDim.x + threadIdx.x;
    if (i >= NNZ) return;
    int r = pos_rows[i], c = pos_cols[i];
    atomicAdd(&g_rowcnt[r], 1);
    atomicAdd(&g_colcnt[c], 1);
    if (i == 0 || pos_rows[i - 1] != r) g_rowstart[r] = i;
    atomicMin(&g_minkey[r], c * NNZ + i);
}

// --------------------------------- exclusive scan of column counts (1 block)
__global__ void col_scan_kernel() {
    __shared__ int partial[256];
    int t = threadIdx.x;
    int local[16];
    int s = 0;
#pragma unroll
    for (int j = 0; j < 16; j++) { local[j] = s; s += g_colcnt[t * 16 + j]; }
    partial[t] = s;
    __syncthreads();
    if (t == 0) {
        int run = 0;
        for (int i = 0; i < 256; i++) { int v = partial[i]; partial[i] = run; run += v; }
    }
    __syncthreads();
    int base = partial[t];
#pragma unroll
    for (int j = 0; j < 16; j++) {
        int off = base + local[j];
        g_coloff[t * 16 + j] = off;
        g_colcur[t * 16 + j] = off;
    }
}

// ----------------------------------------- scatter indices sorted by column
__global__ void scatter_kernel(const int* __restrict__ pos_cols) {
    int i = blockIdx.x * blockDim.x + threadIdx.x;
    if (i >= NNZ) return;
    int c = pos_cols[i];
    int p = atomicAdd(&g_colcur[c], 1);
    g_colperm[p] = i;
}

// --------------------------- fp32 -> bf16 hi/lo plane split (vectorized)
__global__ void split_kernel(const float4* __restrict__ src,
                             __nv_bfloat162* __restrict__ hi,
                             __nv_bfloat162* __restrict__ lo, int n4) {
    int i = blockIdx.x * blockDim.x + threadIdx.x;
    if (i >= n4) return;
    float4 v = src[i];
    __nv_bfloat16 hx = __float2bfloat16_rn(v.x);
    __nv_bfloat16 hy = __float2bfloat16_rn(v.y);
    __nv_bfloat16 hz = __float2bfloat16_rn(v.z);
    __nv_bfloat16 hw = __float2bfloat16_rn(v.w);
    hi[2 * i]     = __halves2bfloat162(hx, hy);
    hi[2 * i + 1] = __halves2bfloat162(hz, hw);
    lo[2 * i]     = __halves2bfloat162(__float2bfloat16_rn(v.x - __bfloat162float(hx)),
                                       __float2bfloat16_rn(v.y - __bfloat162float(hy)));
    lo[2 * i + 1] = __halves2bfloat162(__float2bfloat16_rn(v.z - __bfloat162float(hz)),
                                       __float2bfloat16_rn(v.w - __bfloat162float(hw)));
}

// -------- CfT[n,c] = item_sv_f[c,n]/lam_pos[n] -> bf16 hi/lo [256,4096]
__global__ void cft_kernel(const float* __restrict__ isf,
                           const float* __restrict__ lamp) {
    __shared__ float t[32][33];
    int c_in = blockIdx.x * 32 + threadIdx.y;
    int k_in = blockIdx.y * 32 + threadIdx.x;
    t[threadIdx.y][threadIdx.x] = isf[c_in * Kk + k_in] / lamp[k_in];
    __syncthreads();
    int c_out = blockIdx.x * 32 + threadIdx.x;
    int k_out = blockIdx.y * 32 + threadIdx.y;
    float x = t[threadIdx.x][threadIdx.y];
    __nv_bfloat16 h = __float2bfloat16_rn(x);
    g_CfTH[k_out * Ii + c_out] = h;
    g_CfTL[k_out * Ii + c_out] = __float2bfloat16_rn(x - __bfloat162float(h));
}

// ------------------------------------- user GNN: G_u (rows are presorted)
__global__ void user_gnn_kernel(const int* __restrict__ pos_cols,
                                const float* __restrict__ pos_vals,
                                const float* __restrict__ item_sv,
                                const float* __restrict__ user_sv) {
    int r = blockIdx.x, k = threadIdx.x;
    int s0 = g_rowstart[r], n = g_rowcnt[r];
    __shared__ int sc[256];
    __shared__ float sv[256];
    float acc = 0.0f;
    for (int base = 0; base < n; base += 256) {
        int j = base + k;
        if (j < n) { sc[k] = pos_cols[s0 + j]; sv[k] = pos_vals[s0 + j]; }
        __syncthreads();
        int lim = min(256, n - base);
        for (int jj = 0; jj < lim; jj++)
            acc += sv[jj] * item_sv[sc[jj] * Kk + k];
        __syncthreads();
    }
    g_Gu[r * Kk + k] = 0.5f * (acc * INV_COEFF + user_sv[r * Kk + k]);
}

// ------------- fused item GNN (/lambda folded, transposed) + St, hi/lo out
__global__ void item_s_kernel(const int* __restrict__ pos_rows,
                              const float* __restrict__ pos_vals,
                              const float* __restrict__ user_sv,
                              const float* __restrict__ item_sv,
                              const float* __restrict__ lambda_mat) {
    int c = blockIdx.x, k = threadIdx.x;
    int s0 = g_coloff[c], n = g_colcnt[c];
    __shared__ int sr[256];
    __shared__ float sv[256];
    float accI = 0.0f, accS = 0.0f;
    for (int base = 0; base < n; base += 256) {
        int j = base + k;
        if (j < n) {
            int p = g_colperm[s0 + j];
            sr[k] = pos_rows[p];
            sv[k] = pos_vals[p];
        }
        __syncthreads();
        int lim = min(256, n - base);
        for (int jj = 0; jj < lim; jj++) {
            int r = sr[jj];
            float v = sv[jj];
            accI += v * user_sv[r * Kk + k];
            accS += v * g_Gu[r * Kk + k];
        }
        __syncthreads();
    }
    float gi = 0.5f * (accI * INV_COEFF + item_sv[c * Kk + k]) / lambda_mat[k];
    __nv_bfloat16 gih = __float2bfloat16_rn(gi);
    g_GiTH[k * Ii + c] = gih;
    g_GiTL[k * Ii + c] = __float2bfloat16_rn(gi - __bfloat162float(gih));
    __nv_bfloat16 sh = __float2bfloat16_rn(accS);
    g_StH[c * Kk + k] = sh;
    g_StL[c * Kk + k] = __float2bfloat16_rn(accS - __bfloat162float(sh));
}

// ===================== mma.sync bf16-split GEMM ============================
// D[M,N] = A[M,K] @ B[N,K]^T via 3-term bf16 split, fp32 accumulation.
// BM=BN=128, BK=32, 256 threads (8 warps, 2x4), warp tile 64x32.
// MODE 0: store fp32 C.  MODE 1: per-column min/sum atomics (stats).
// MODE 2: store fp32 C + bf16 hi/lo planes.

__device__ __forceinline__ void cp16(uint32_t dst, const void* src) {
    asm volatile("cp.async.cg.shared.global [%0], [%1], 16;"
                 :: "r"(dst), "l"(__cvta_generic_to_global(src)));
}
#define CP_COMMIT() asm volatile("cp.async.commit_group;")
#define CP_WAIT1()  asm volatile("cp.async.wait_group 1;")

__device__ __forceinline__ uint32_t smem_u32(const void* p) {
    uint32_t a;
    asm("{ .reg .u64 t; cvta.to.shared.u64 t, %1; cvt.u32.u64 %0, t; }"
        : "=r"(a) : "l"(p));
    return a;
}

#define MMA_BF16(d, a, b) \
    asm volatile("mma.sync.aligned.m16n8k16.row.col.f32.bf16.bf16.f32 " \
        "{%0,%1,%2,%3}, {%4,%5,%6,%7}, {%8,%9}, {%0,%1,%2,%3};" \
        : "+f"((d)[0]), "+f"((d)[1]), "+f"((d)[2]), "+f"((d)[3]) \
        : "r"((a)[0]), "r"((a)[1]), "r"((a)[2]), "r"((a)[3]), \
          "r"((b)[0]), "r"((b)[1]))

// SMEM per stage: 4 planes (Ahi, Alo, Bhi, Blo), each 128 rows x 64B.
#define PLANE 8192
#define STAGE 32768

template <int MODE>
__device__ __forceinline__ void gemm_core(
    int M, int N, int K,
    const __nv_bfloat16* __restrict__ AH, const __nv_bfloat16* __restrict__ AL,
    const __nv_bfloat16* __restrict__ BH, const __nv_bfloat16* __restrict__ BL,
    float* __restrict__ C,
    __nv_bfloat16* __restrict__ CH, __nv_bfloat16* __restrict__ CL,
    unsigned* cmin, float* csum, char* dsm)
{
    __shared__ unsigned sMin[128];
    __shared__ float sSum[128];

    int tid = threadIdx.x;
    int l = tid & 31, wid = tid >> 5;
    int wm = wid >> 2, wn = wid & 3;             // 2 x 4 warps
    int m0 = blockIdx.y * 128, n0 = blockIdx.x * 128;

    if (MODE == 1 && tid < 128) { sMin[tid] = 0xFFFFFFFFu; sSum[tid] = 0.0f; }

    float acc[4][4][4];
#pragma unroll
    for (int a = 0; a < 4; a++)
#pragma unroll
        for (int b = 0; b < 4; b++)
#pragma unroll
            for (int c = 0; c < 4; c++) acc[a][b][c] = 0.0f;

    uint32_t sb = smem_u32(dsm);
    int r_ld = tid >> 1;                   // row 0..127 (shared by A & B planes)
    int cb_ld = (tid & 1) * 2;             // 16B-chunk base (0 or 2)
    int csw = (r_ld >> 1) & 3;             // chunk swizzle for this row

    int NIT = K >> 5;

    // ---- async stage loader (A: m0 rows; B: n0 rows; 32 k-elems) ----
    auto load_stage = [&](int s, int it) {
        uint32_t stb = sb + s * STAGE;
        int k0 = it << 5;
        const __nv_bfloat16* ah = AH + (size_t)(m0 + r_ld) * K + k0;
        const __nv_bfloat16* al = AL + (size_t)(m0 + r_ld) * K + k0;
        const __nv_bfloat16* bh = BH + (size_t)(n0 + r_ld) * K + k0;
        const __nv_bfloat16* bl = BL + (size_t)(n0 + r_ld) * K + k0;
#pragma unroll
        for (int c = cb_ld; c < cb_ld + 2; c++) {
            uint32_t off = r_ld * 64 + (c ^ csw) * 16;
            cp16(stb + off,             ah + c * 8);
            cp16(stb + PLANE + off,     al + c * 8);
            cp16(stb + 2 * PLANE + off, bh + c * 8);
            cp16(stb + 3 * PLANE + off, bl + c * 8);
        }
    };

    load_stage(0, 0);
    CP_COMMIT();

    for (int it = 0; it < NIT; it++) {
        if (it + 1 < NIT) load_stage((it + 1) & 1, it + 1);
        CP_COMMIT();
        CP_WAIT1();
        __syncthreads();

        const char* st = dsm + (it & 1) * STAGE;
#pragma unroll
        for (int ks = 0; ks < 2; ks++) {
            uint32_t ah[4][4], al4[4][4], bh[4][2], bl4[4][2];
#pragma unroll
            for (int mt = 0; mt < 4; mt++) {
                int row = wm * 64 + mt * 16 + (l >> 2);
                int f = (row & 6) << 1;
                int cp0 = ks * 8 + (l & 3);
                uint32_t o00 = row * 64 + ((cp0 ^ f) << 2);
                uint32_t o01 = row * 64 + (((cp0 + 4) ^ f) << 2);
                uint32_t o10 = (row + 8) * 64 + ((cp0 ^ f) << 2);
                uint32_t o11 = (row + 8) * 64 + (((cp0 + 4) ^ f) << 2);
                ah[mt][0] = *(const uint32_t*)(st + o00);
                ah[mt][1] = *(const uint32_t*)(st + o10);
                ah[mt][2] = *(const uint32_t*)(st + o01);
                ah[mt][3] = *(const uint32_t*)(st + o11);
                al4[mt][0] = *(const uint32_t*)(st + PLANE + o00);
                al4[mt][1] = *(const uint32_t*)(st + PLANE + o10);
                al4[mt][2] = *(const uint32_t*)(st + PLANE + o01);
                al4[mt][3] = *(const uint32_t*)(st + PLANE + o11);
            }
#pragma unroll
            for (int nt = 0; nt < 4; nt++) {
                int row = wn * 32 + nt * 8 + (l >> 2);
                int f = (row & 6) << 1;
                int cp0 = ks * 8 + (l & 3);
                uint32_t o0 = row * 64 + ((cp0 ^ f) << 2);
                uint32_t o1 = row * 64 + (((cp0 + 4) ^ f) << 2);
                bh[nt][0] = *(const uint32_t*)(st + 2 * PLANE + o0);
                bh[nt][1] = *(const uint32_t*)(st + 2 * PLANE + o1);
                bl4[nt][0] = *(const uint32_t*)(st + 3 * PLANE + o0);
                bl4[nt][1] = *(const uint32_t*)(st + 3 * PLANE + o1);
            }
#pragma unroll
            for (int mt = 0; mt < 4; mt++)
#pragma unroll
                for (int nt = 0; nt < 4; nt++) {
                    MMA_BF16(acc[mt][nt], ah[mt], bh[nt]);
                    MMA_BF16(acc[mt][nt], ah[mt], bl4[nt]);
                    MMA_BF16(acc[mt][nt], al4[mt], bh[nt]);
                }
        }
        __syncthreads();
    }

    // ---------------- epilogue ----------------
    if (MODE == 0 || MODE == 2) {
#pragma unroll
        for (int mt = 0; mt < 4; mt++) {
            int row = m0 + wm * 64 + mt * 16 + (l >> 2);
#pragma unroll
            for (int nt = 0; nt < 4; nt++) {
                int col = n0 + wn * 32 + nt * 8 + ((l & 3) << 1);
                float v0 = acc[mt][nt][0], v1 = acc[mt][nt][1];
                float v2 = acc[mt][nt][2], v3 = acc[mt][nt][3];
                *(float2*)&C[(size_t)row * N + col] = make_float2(v0, v1);
                *(float2*)&C[(size_t)(row + 8) * N + col] = make_float2(v2, v3);
                if (MODE == 2) {
                    __nv_bfloat16 h0 = __float2bfloat16_rn(v0);
                    __nv_bfloat16 h1 = __float2bfloat16_rn(v1);
                    __nv_bfloat16 h2 = __float2bfloat16_rn(v2);
                    __nv_bfloat16 h3 = __float2bfloat16_rn(v3);
                    *(__nv_bfloat162*)&CH[(size_t)row * N + col] = __halves2bfloat162(h0, h1);
                    *(__nv_bfloat162*)&CH[(size_t)(row + 8) * N + col] = __halves2bfloat162(h2, h3);
                    *(__nv_bfloat162*)&CL[(size_t)row * N + col] =
                        __halves2bfloat162(__float2bfloat16_rn(v0 - __bfloat162float(h0)),
                                           __float2bfloat16_rn(v1 - __bfloat162float(h1)));
                    *(__nv_bfloat162*)&CL[(size_t)(row + 8) * N + col] =
                        __halves2bfloat162(__float2bfloat16_rn(v2 - __bfloat162float(h2)),
                                           __float2bfloat16_rn(v3 - __bfloat162float(h3)));
                }
            }
        }
    } else {   // MODE 1: fused column min/sum
#pragma unroll
        for (int nt = 0; nt < 4; nt++) {
            float mn0 = acc[0][nt][0], sm0 = 0.0f;
            float mn1 = acc[0][nt][1], sm1 = 0.0f;
#pragma unroll
            for (int mt = 0; mt < 4; mt++) {
                mn0 = fminf(mn0, fminf(acc[mt][nt][0], acc[mt][nt][2]));
                sm0 += acc[mt][nt][0] + acc[mt][nt][2];
                mn1 = fminf(mn1, fminf(acc[mt][nt][1], acc[mt][nt][3]));
                sm1 += acc[mt][nt][1] + acc[mt][nt][3];
            }
#pragma unroll
            for (int d = 4; d < 32; d <<= 1) {
                sm0 += __shfl_xor_sync(0xFFFFFFFFu, sm0, d);
                sm1 += __shfl_xor_sync(0xFFFFFFFFu, sm1, d);
                mn0 = fminf(mn0, __shfl_xor_sync(0xFFFFFFFFu, mn0, d));
                mn1 = fminf(mn1, __shfl_xor_sync(0xFFFFFFFFu, mn1, d));
            }
            if ((l >> 2) == 0) {
                int c = wn * 32 + nt * 8 + ((l & 3) << 1);
                atomicMin(&sMin[c], fenc(mn0));
                atomicAdd(&sSum[c], sm0);
                atomicMin(&sMin[c + 1], fenc(mn1));
                atomicAdd(&sSum[c + 1], sm1);
            }
        }
        __syncthreads();
        if (tid < 128) {
            atomicMin(&cmin[n0 + tid], sMin[tid]);
            atomicAdd(&csum[n0 + tid], sSum[tid]);
        }
    }
}

// wrappers
struct G12P {
    const __nv_bfloat16 *AH[2], *AL[2], *BH[2], *BL[2];
    float* C[2];
    __nv_bfloat16 *CH[2], *CL[2];
};

__global__ void __launch_bounds__(256, 1) gemm12_kernel(G12P p) {
    extern __shared__ char dsm[];
    int z = blockIdx.z;
    gemm_core<2>(Uu, Kk, Ii, p.AH[z], p.AL[z], p.BH[z], p.BL[z],
                 p.C[z], p.CH[z], p.CL[z], nullptr, nullptr, dsm);
}

__global__ void __launch_bounds__(256, 1) gemm_stats_kernel(
    const __nv_bfloat16* AH, const __nv_bfloat16* AL,
    const __nv_bfloat16* BH, const __nv_bfloat16* BL,
    unsigned* cmin, float* csum) {
    extern __shared__ char dsm[];
    gemm_core<1>(Uu, Ii, Kk, AH, AL, BH, BL,
                 nullptr, nullptr, nullptr, cmin, csum, dsm);
}

__global__ void __launch_bounds__(256, 1) gemm_out_kernel(
    const __nv_bfloat16* AH, const __nv_bfloat16* AL,
    const __nv_bfloat16* BH, const __nv_bfloat16* BL,
    float* C) {
    extern __shared__ char dsm[];
    gemm_core<0>(Uu, Ii, Kk, AH, AL, BH, BL,
                 C, nullptr, nullptr, nullptr, nullptr, dsm);
}

// ------------------- per-row mat_expo entries -> p1/p2 (compute_P fusion)
__global__ void entry_kernel(const int* __restrict__ pos_cols,
                             const float* __restrict__ pos_vals,
                             const float* __restrict__ usf) {
    int r = blockIdx.x, t = threadIdx.x;
    int mk = g_minkey[r];
    if (mk == 0x7FFFFFFF) { if (t == 0) g_has[r] = 0; return; }
    int eidx = mk % NNZ;
    int c1 = pos_cols[eidx];
    float v1 = pos_vals[eidx];
    int c2 = (c1 + 1) & (Ii - 1);
    float a = g_E1[r * Kk + t];
    float e1 = a * usf[c1 * Kk + t];
    float e2 = a * usf[c2 * Kk + t];
    __shared__ float s1[256], s2[256];
    s1[t] = e1; s2[t] = e2;
    __syncthreads();
    for (int off = 128; off > 0; off >>= 1) {
        if (t < off) { s1[t] += s1[t + off]; s2[t] += s2[t + off]; }
        __syncthreads();
    }
    if (t == 0) {
        float E1v = s1[0], E2v = s2[0];
        float m1 = fdec(g_colmin[c1]), m2 = fdec(g_colmin[c2]);
        float sum1 = g_colsum[c1] - (float)Uu * m1 + (float)Uu * 1e-8f;
        float sum2 = g_colsum[c2] - (float)Uu * m2 + (float)Uu * 1e-8f;
        float n1 = (E1v - m1 + 1e-8f) / sum1;
        float n2 = (E2v - m2 + 1e-8f) / sum2;
        float d1 = (v1 == 0.0f) ? 1e-5f : v1;
        float d2 = (v1 == 0.0f) ? 1e-5f : -v1;
        g_p1[r] = n1 / d1;
        g_p2[r] = n2 / d2;
        g_c1[r] = c1;
        g_c2[r] = c2;
        g_has[r] = 1;
    }
}

// ------------------------------------------- out += 0.2 * mat_adjust
__global__ void adjust_kernel(float* __restrict__ out) {
    int r = blockIdx.x * blockDim.x + threadIdx.x;
    if (r >= Uu || !g_has[r]) return;
    out[(size_t)r * Ii + g_c1[r]] += 0.2f * g_p1[r];
    out[(size_t)r * Ii + g_c2[r]] += 0.2f * g_p2[r];
}

extern "C" void kernel_launch(void* const* d_in, const int* in_sizes, int n_in,
                              void* d_out, int out_size) {
    const float* adj       = (const float*)d_in[0];
    const float* norm_adj  = (const float*)d_in[1];
    const float* user_sv   = (const float*)d_in[2];
    const float* item_sv   = (const float*)d_in[3];
    const float* user_sv_f = (const float*)d_in[4];
    const float* item_sv_f = (const float*)d_in[5];
    const int*   pos_rows  = (const int*)d_in[6];
    const int*   pos_cols  = (const int*)d_in[7];
    const float* pos_vals  = (const float*)d_in[8];
    const float* lambda_m  = (const float*)d_in[9];
    const float* lambda_p  = (const float*)d_in[10];
    float* out = (float*)d_out;

    void *adjH, *adjL, *nrmH, *nrmL, *cfH, *cfL, *giH, *giL;
    void *usH, *usL, *stH, *stL, *e1H, *e1L, *e2H, *e2L, *e1f, *e2f;
    void *cminp, *csump;
    cudaGetSymbolAddress(&adjH, g_adjH); cudaGetSymbolAddress(&adjL, g_adjL);
    cudaGetSymbolAddress(&nrmH, g_nrmH); cudaGetSymbolAddress(&nrmL, g_nrmL);
    cudaGetSymbolAddress(&cfH, g_CfTH);  cudaGetSymbolAddress(&cfL, g_CfTL);
    cudaGetSymbolAddress(&giH, g_GiTH);  cudaGetSymbolAddress(&giL, g_GiTL);
    cudaGetSymbolAddress(&usH, g_usfH);  cudaGetSymbolAddress(&usL, g_usfL);
    cudaGetSymbolAddress(&stH, g_StH);   cudaGetSymbolAddress(&stL, g_StL);
    cudaGetSymbolAddress(&e1H, g_E1H);   cudaGetSymbolAddress(&e1L, g_E1L);
    cudaGetSymbolAddress(&e2H, g_E2H);   cudaGetSymbolAddress(&e2L, g_E2L);
    cudaGetSymbolAddress(&e1f, g_E1);    cudaGetSymbolAddress(&e2f, g_E2);
    cudaGetSymbolAddress(&cminp, g_colmin); cudaGetSymbolAddress(&csump, g_colsum);

    cudaFuncSetAttribute(gemm12_kernel, cudaFuncAttributeMaxDynamicSharedMemorySize, 65536);
    cudaFuncSetAttribute(gemm_stats_kernel, cudaFuncAttributeMaxDynamicSharedMemorySize, 65536);
    cudaFuncSetAttribute(gemm_out_kernel, cudaFuncAttributeMaxDynamicSharedMemorySize, 65536);

    // 1. metadata init
    init_kernel<<<Uu / 256, 256>>>();
    // 2. row/col counts, row starts, per-row min key
    build_kernel<<<(NNZ + 255) / 256, 256>>>(pos_rows, pos_cols);
    // 3. column offsets (counting sort)
    col_scan_kernel<<<1, 256>>>();
    // 4. column-sorted permutation
    scatter_kernel<<<(NNZ + 255) / 256, 256>>>(pos_cols);
    // 5. operand prep: bf16 hi/lo planes
    split_kernel<<<(Uu * Ii / 4 + 255) / 256, 256>>>(
        (const float4*)adj, (__nv_bfloat162*)adjH, (__nv_bfloat162*)adjL, Uu * Ii / 4);
    split_kernel<<<(Uu * Ii / 4 + 255) / 256, 256>>>(
        (const float4*)norm_adj, (__nv_bfloat162*)nrmH, (__nv_bfloat162*)nrmL, Uu * Ii / 4);
    split_kernel<<<(Ii * Kk / 4 + 255) / 256, 256>>>(
        (const float4*)user_sv_f, (__nv_bfloat162*)usH, (__nv_bfloat162*)usL, Ii * Kk / 4);
    cft_kernel<<<dim3(Ii / 32, Kk / 32), dim3(32, 32)>>>(item_sv_f, lambda_p);
    // 6. user GNN smoothing
    user_gnn_kernel<<<Uu, 256>>>(pos_cols, pos_vals, item_sv, user_sv);
    // 7. fused item GNN (-> GiT hi/lo) + St = (G_u^T @ pos_dense)^T hi/lo
    item_s_kernel<<<Ii, 256>>>(pos_rows, pos_vals, user_sv, item_sv, lambda_m);
    // 8+9. E1 = adj @ CfT^T, E2 = norm_adj @ GiT^T  (merged, grid.z = 2)
    {
        G12P p;
        p.AH[0] = (const __nv_bfloat16*)adjH; p.AL[0] = (const __nv_bfloat16*)adjL;
        p.BH[0] = (const __nv_bfloat16*)cfH;  p.BL[0] = (const __nv_bfloat16*)cfL;
        p.C[0] = (float*)e1f;
        p.CH[0] = (__nv_bfloat16*)e1H; p.CL[0] = (__nv_bfloat16*)e1L;
        p.AH[1] = (const __nv_bfloat16*)nrmH; p.AL[1] = (const __nv_bfloat16*)nrmL;
        p.BH[1] = (const __nv_bfloat16*)giH;  p.BL[1] = (const __nv_bfloat16*)giL;
        p.C[1] = (float*)e2f;
        p.CH[1] = (__nv_bfloat16*)e2H; p.CL[1] = (__nv_bfloat16*)e2L;
        gemm12_kernel<<<dim3(Kk / 128, Uu / 128, 2), 256, 65536>>>(p);
    }
    // 10. mat_expo column stats: E1 @ user_sv_f[:Ii]^T, fused min/sum
    gemm_stats_kernel<<<dim3(Ii / 128, Uu / 128), 256, 65536>>>(
        (const __nv_bfloat16*)e1H, (const __nv_bfloat16*)e1L,
        (const __nv_bfloat16*)usH, (const __nv_bfloat16*)usL,
        (unsigned*)cminp, (float*)csump);
    // 11. per-row mat_expo entries -> p1/p2
    entry_kernel<<<Uu, 256>>>(pos_cols, pos_vals, user_sv_f);
    // 12. out = E2 @ St^T
    gemm_out_kernel<<<dim3(Ii / 128, Uu / 128), 256, 65536>>>(
        (const __nv_bfloat16*)e2H, (const __nv_bfloat16*)e2L,
        (const __nv_bfloat16*)stH, (const __nv_bfloat16*)stL, out);
    // 13. out += 0.2 * mat_adjust
    adjust_kernel<<<Uu / 256, 256>>>(out);
}